// round 1
// baseline (speedup 1.0000x reference)
#include <cuda_runtime.h>
#include <math.h>
#include <stdint.h>

// Problem dims
#define BB 32
#define TT 512
#define II 128
#define HH 512
#define OO 128

// ---------------- device scratch (no allocs allowed) ----------------
__device__ float    g_pre [TT * HH * BB];   // [T][H][B] 32MB (reused pre0/pre1)
__device__ float    g_traj[TT * HH * BB];   // [T][H][B] 32MB (h1, then reused as h2)
__device__ float    g_tmp [TT * OO * BB];   // [T][O][B]  8MB (fc pre-transpose)
__device__ float    g_hping[4 * HH * BB];   // 2 ping-pong pairs (layer0, layer1)
__device__ unsigned g_counters[1024];       // per-step barrier counters (512 per layer)

// ---------------- init: zero counters + h0 buffers each replay ----------------
__global__ void init_kernel(unsigned* counters, float* hping) {
    int i = blockIdx.x * blockDim.x + threadIdx.x;
    int stride = gridDim.x * blockDim.x;
    for (int e = i; e < 1024; e += stride) counters[e] = 0u;
    for (int e = i; e < 4 * HH * BB; e += stride) hping[e] = 0.0f;
}

// ---------------- generic fp32 GEMM: C[t][j][b] = bias(j) + sum_k A(t,k,b)*W[j][k] ----------------
// grid: (N/64, T), block: 128 threads. Tile 64j x 32b, microtile 4x4.
__global__ void __launch_bounds__(128)
gemm_pre_kernel(const float* __restrict__ A, const float* __restrict__ W,
                const float* __restrict__ bias1, const float* __restrict__ bias2,
                float* __restrict__ C,
                int K, long sAt, long sAk, long sAb, int N)
{
    __shared__ float Ws[32][68];   // [k][j] padded
    __shared__ float As[32][36];   // [k][b] padded

    const int t   = blockIdx.y;
    const int j0  = blockIdx.x * 64;
    const int tid = threadIdx.x;
    const int jg  = tid & 15;      // 16 j-groups of 4
    const int bg  = tid >> 4;      // 8 b-groups of 4

    float acc[4][4];
#pragma unroll
    for (int a = 0; a < 4; a++)
#pragma unroll
        for (int b = 0; b < 4; b++) acc[a][b] = 0.0f;

    for (int kt = 0; kt < K; kt += 32) {
        __syncthreads();
        // stage W tile (transposed): 64 rows x 32 k
        {
            const int jr = tid >> 1;
            const int kc = (tid & 1) * 16;
            const float* wp = &W[(size_t)(j0 + jr) * K + kt + kc];
#pragma unroll
            for (int i = 0; i < 16; i += 4) {
                float4 v = *(const float4*)(wp + i);
                Ws[kc + i + 0][jr] = v.x;
                Ws[kc + i + 1][jr] = v.y;
                Ws[kc + i + 2][jr] = v.z;
                Ws[kc + i + 3][jr] = v.w;
            }
        }
        // stage A tile: 32 k x 32 b
        if (sAb == 1) {   // b-contiguous (trajectory layout [t][k][b])
#pragma unroll
            for (int i = 0; i < 2; i++) {
                int f = tid + i * 128;
                int k = f >> 3, b4 = (f & 7) * 4;
                float4 v = *(const float4*)&A[(size_t)t * sAt + (size_t)(kt + k) * sAk + b4];
                *(float4*)&As[k][b4] = v;
            }
        } else {          // k-contiguous (inputs layout [b][t][i])
#pragma unroll
            for (int i = 0; i < 2; i++) {
                int f = tid + i * 128;
                int b = f >> 3, kq = (f & 7) * 4;
                float4 v = *(const float4*)&A[(size_t)b * sAb + (size_t)t * sAt + kt + kq];
                As[kq + 0][b] = v.x;
                As[kq + 1][b] = v.y;
                As[kq + 2][b] = v.z;
                As[kq + 3][b] = v.w;
            }
        }
        __syncthreads();
#pragma unroll
        for (int k = 0; k < 32; k++) {
            const float4 w = *(const float4*)&Ws[k][jg * 4];
            const float4 a = *(const float4*)&As[k][bg * 4];
            acc[0][0] += w.x * a.x; acc[0][1] += w.x * a.y; acc[0][2] += w.x * a.z; acc[0][3] += w.x * a.w;
            acc[1][0] += w.y * a.x; acc[1][1] += w.y * a.y; acc[1][2] += w.y * a.z; acc[1][3] += w.y * a.w;
            acc[2][0] += w.z * a.x; acc[2][1] += w.z * a.y; acc[2][2] += w.z * a.z; acc[2][3] += w.z * a.w;
            acc[3][0] += w.w * a.x; acc[3][1] += w.w * a.y; acc[3][2] += w.w * a.z; acc[3][3] += w.w * a.w;
        }
    }

#pragma unroll
    for (int ji = 0; ji < 4; ji++) {
        int j = j0 + jg * 4 + ji;
        float bb = bias1 ? bias1[j] : 0.0f;
        if (bias2) bb += bias2[j];
        float4 o = make_float4(acc[ji][0] + bb, acc[ji][1] + bb, acc[ji][2] + bb, acc[ji][3] + bb);
        *(float4*)&C[(size_t)t * N * BB + (size_t)j * BB + bg * 4] = o;
    }
}

// ---------------- persistent recurrence layer ----------------
// grid: 128 CTAs (all co-resident on 148 SMs), block: 128 threads.
// CTA owns 4 hidden columns. h buffers are [H][B] (k-major). One software grid
// barrier per timestep via per-step counters.
__global__ void __launch_bounds__(128)
rnn_layer_kernel(const float* __restrict__ pre, float* __restrict__ traj,
                 const float* __restrict__ W,
                 float* buf0, float* buf1, unsigned* counters)
{
    __shared__ float Wt[16][32][4];   // [kk][kseg][jj] : conflict-free compute reads, 8KB
    __shared__ float ps[32][132];     // partials [kseg][out], padded

    const int tid  = threadIdx.x;
    const int j0   = blockIdx.x * 4;
    const int bg   = tid & 3;
    const int kseg = tid >> 2;        // 0..31
    const int b0   = bg * 8;

    // preload W slice: Wt[kk][kseg][jj] = W[(j0+jj)*H + kseg*16 + kk]
    for (int e = tid; e < 2048; e += 128) {
        int jj = e & 3;
        int ks = (e >> 2) & 31;
        int kk = e >> 7;
        Wt[kk][ks][jj] = W[(size_t)(j0 + jj) * HH + ks * 16 + kk];
    }
    __syncthreads();

    const int out_b  = tid >> 2;      // output this thread finalizes
    const int out_jj = tid & 3;

    for (int t = 0; t < TT; t++) {
        const float* hb = (t & 1) ? buf1 : buf0;
        float*       hn = (t & 1) ? buf0 : buf1;

        // prefetch pre-activation for this thread's output
        const float preval = pre[(size_t)t * (HH * BB) + (size_t)(j0 + out_jj) * BB + out_b];

        float acc[8][4];
#pragma unroll
        for (int a = 0; a < 8; a++)
#pragma unroll
            for (int b = 0; b < 4; b++) acc[a][b] = 0.0f;

#pragma unroll
        for (int kk = 0; kk < 16; kk++) {
            const int k = kseg * 16 + kk;
            const float4 w  = *(const float4*)&Wt[kk][kseg][0];
            const float4 hA = __ldcg((const float4*)(hb + (k << 5) + b0));
            const float4 hB = __ldcg((const float4*)(hb + (k << 5) + b0 + 4));
            acc[0][0] += hA.x * w.x; acc[0][1] += hA.x * w.y; acc[0][2] += hA.x * w.z; acc[0][3] += hA.x * w.w;
            acc[1][0] += hA.y * w.x; acc[1][1] += hA.y * w.y; acc[1][2] += hA.y * w.z; acc[1][3] += hA.y * w.w;
            acc[2][0] += hA.z * w.x; acc[2][1] += hA.z * w.y; acc[2][2] += hA.z * w.z; acc[2][3] += hA.z * w.w;
            acc[3][0] += hA.w * w.x; acc[3][1] += hA.w * w.y; acc[3][2] += hA.w * w.z; acc[3][3] += hA.w * w.w;
            acc[4][0] += hB.x * w.x; acc[4][1] += hB.x * w.y; acc[4][2] += hB.x * w.z; acc[4][3] += hB.x * w.w;
            acc[5][0] += hB.y * w.x; acc[5][1] += hB.y * w.y; acc[5][2] += hB.y * w.z; acc[5][3] += hB.y * w.w;
            acc[6][0] += hB.z * w.x; acc[6][1] += hB.z * w.y; acc[6][2] += hB.z * w.z; acc[6][3] += hB.z * w.w;
            acc[7][0] += hB.w * w.x; acc[7][1] += hB.w * w.y; acc[7][2] += hB.w * w.z; acc[7][3] += hB.w * w.w;
        }

        // dump partials: out index = b*4 + jj
#pragma unroll
        for (int bi = 0; bi < 8; bi++) {
            *(float4*)&ps[kseg][(bg * 8 + bi) * 4] =
                make_float4(acc[bi][0], acc[bi][1], acc[bi][2], acc[bi][3]);
        }
        __syncthreads();

        // reduce 32 k-segments for output 'tid'
        float s = 0.0f;
#pragma unroll
        for (int ss = 0; ss < 32; ss++) s += ps[ss][tid];

        const float val = tanhf(preval + s);
        const int jdx = j0 + out_jj;
        hn[(size_t)jdx * BB + out_b] = val;
        traj[(size_t)t * (HH * BB) + (size_t)jdx * BB + out_b] = val;

        __threadfence();
        __syncthreads();   // all stores + fences done; also guards ps reuse

        if (tid == 0) {
            unsigned arrived = atomicAdd(&counters[t], 1u) + 1u;
            if (arrived < 128u) {
                volatile unsigned* p = &counters[t];
                while (*p < 128u) { __nanosleep(40); }
            }
        }
        __syncthreads();
    }
}

// ---------------- transpose: g_tmp [T][O][B] -> out [B][O][T] ----------------
__global__ void transpose_kernel(const float* __restrict__ tmp, float* __restrict__ out)
{
    __shared__ float s[32][33];
    const int t0 = blockIdx.x * 32;
    const int o  = blockIdx.y;
    const int tx = threadIdx.x;   // 32
    const int ty = threadIdx.y;   // 8
#pragma unroll
    for (int i = 0; i < 4; i++) {
        int tt = t0 + ty + i * 8;
        s[ty + i * 8][tx] = tmp[(size_t)tt * (OO * BB) + (size_t)o * BB + tx];
    }
    __syncthreads();
#pragma unroll
    for (int i = 0; i < 4; i++) {
        int b = ty + i * 8;
        out[(size_t)b * (OO * TT) + (size_t)o * TT + t0 + tx] = s[tx][b];
    }
}

// ---------------- launch ----------------
extern "C" void kernel_launch(void* const* d_in, const int* in_sizes, int n_in,
                              void* d_out, int out_size)
{
    const float* inputs = (const float*)d_in[0];
    const float* W_ih0  = (const float*)d_in[1];
    const float* W_hh0  = (const float*)d_in[2];
    const float* b_ih0  = (const float*)d_in[3];
    const float* b_hh0  = (const float*)d_in[4];
    const float* W_ih1  = (const float*)d_in[5];
    const float* W_hh1  = (const float*)d_in[6];
    const float* b_ih1  = (const float*)d_in[7];
    const float* b_hh1  = (const float*)d_in[8];
    const float* W_fc   = (const float*)d_in[9];
    const float* b_fc   = (const float*)d_in[10];

    float *pre, *traj, *tmp, *hping;
    unsigned* counters;
    cudaGetSymbolAddress((void**)&pre,      g_pre);
    cudaGetSymbolAddress((void**)&traj,     g_traj);
    cudaGetSymbolAddress((void**)&tmp,      g_tmp);
    cudaGetSymbolAddress((void**)&hping,    g_hping);
    cudaGetSymbolAddress((void**)&counters, g_counters);

    init_kernel<<<64, 256>>>(counters, hping);

    // pre0[t][j][b] = inputs[b][t][:] . W_ih0[j][:] + b_ih0[j] + b_hh0[j]
    gemm_pre_kernel<<<dim3(8, TT), 128>>>(inputs, W_ih0, b_ih0, b_hh0, pre,
                                          II, (long)II, 1L, (long)TT * II, HH);

    // layer 0 recurrence -> h1 trajectory
    rnn_layer_kernel<<<128, 128>>>(pre, traj, W_hh0,
                                   hping, hping + HH * BB, counters);

    // pre1[t][j][b] = h1[t][:][b] . W_ih1[j][:] + b_ih1[j] + b_hh1[j]
    gemm_pre_kernel<<<dim3(8, TT), 128>>>(traj, W_ih1, b_ih1, b_hh1, pre,
                                          HH, (long)HH * BB, (long)BB, 1L, HH);

    // layer 1 recurrence -> h2 trajectory (reuses g_traj)
    rnn_layer_kernel<<<128, 128>>>(pre, traj, W_hh1,
                                   hping + 2 * HH * BB, hping + 3 * HH * BB,
                                   counters + 512);

    // fc: tmp[t][o][b] = h2[t][:][b] . W_fc[o][:] + b_fc[o]
    gemm_pre_kernel<<<dim3(2, TT), 128>>>(traj, W_fc, b_fc, nullptr, tmp,
                                          HH, (long)HH * BB, (long)BB, 1L, OO);

    // out[b][o][t] = tmp[t][o][b]
    transpose_kernel<<<dim3(16, OO), dim3(32, 8)>>>(tmp, (float*)d_out);
}